// round 2
// baseline (speedup 1.0000x reference)
#include <cuda_runtime.h>
#include <cub/cub.cuh>
#include <cstdint>

#define B_    8
#define L_    1024
#define H_    768
#define E_    16
#define W_    504
#define DFF_  512
#define NSPAN 5982
#define NE_   (NSPAN*E_)        /* 95712 */
#define BNE_  (B_*NE_)          /* 765696 */

// ---------------- scratch (device globals; no runtime allocation) ----------
__device__ float g_word_emb[B_*W_*H_];
__device__ int   g_cnt[B_*W_];
__device__ int   g_entpos[B_*E_];
__device__ float g_h1[B_*E_*DFF_];
__device__ float g_entvec[B_*E_*H_];
__device__ float g_G[B_*E_*DFF_];               // span_w2 @ ent_vec^T
__device__ float g_c[B_*E_];                    // span_b2 . ent_vec
__device__ float g_Bpack[H_*2*DFF_];            // [768,1024] packed span_w1
__device__ float g_PQ[B_*W_*2*DFF_];            // per word: P(512) | Q(512)
__device__ int   g_sstart[NSPAN];
__device__ int   g_send[NSPAN];
__device__ unsigned long long g_keys_in[BNE_];
__device__ unsigned long long g_keys_out[BNE_];
__device__ __align__(256) unsigned char g_cub_temp[64u*1024u*1024u];

// ---------------- setup: zero accumulators + span table --------------------
__global__ void k_setup() {
    int i = blockIdx.x * blockDim.x + threadIdx.x;
    int stride = gridDim.x * blockDim.x;
    for (int t = i; t < B_*W_*H_; t += stride) g_word_emb[t] = 0.f;
    for (int t = i; t < B_*W_;    t += stride) g_cnt[t] = 0;
    for (int n = i; n < NSPAN;    n += stride) {
        int s, e;
        if (n < 5916) { s = n / 12; e = s + n % 12; }
        else {
            int r = n - 5916; s = 493;
            while (r >= W_ - s) { r -= W_ - s; s++; }
            e = s + r;
        }
        g_sstart[n] = s; g_send[n] = e;
    }
}

// ---------------- word mean pooling (scatter-add) ---------------------------
__global__ void k_pool(const float* __restrict__ hs, const int* __restrict__ tmask,
                       const int* __restrict__ widx) {
    int t = blockIdx.x;
    if (tmask[t] != 1) return;
    int w = widx[t];
    if (w < 0 || w >= W_) return;
    int b = t >> 10;
    float* dst = &g_word_emb[((size_t)b*W_ + w) * H_];
    const float* src = &hs[(size_t)t * H_];
    for (int h = threadIdx.x; h < H_; h += blockDim.x) atomicAdd(&dst[h], src[h]);
    if (threadIdx.x == 0) atomicAdd(&g_cnt[b*W_ + w], 1);
}

__global__ void k_pooldiv() {
    int i = blockIdx.x * blockDim.x + threadIdx.x;
    int stride = gridDim.x * blockDim.x;
    for (int t = i; t < B_*W_*H_; t += stride) {
        int cnt = g_cnt[t / H_];
        g_word_emb[t] /= (float)(cnt > 1 ? cnt : 1);
    }
}

// ---------------- entity positions (stable: entities asc, then rest asc) ---
__global__ void k_entscan(const int* __restrict__ emask) {
    const unsigned FULL = 0xffffffffu;
    int warp = threadIdx.x >> 5, lane = threadIdx.x & 31;
    if (warp >= B_) return;
    int b = warp, cnt = 0;
    for (int pass = 0; pass < 2 && cnt < E_; pass++) {
        for (int base = 0; base < L_ && cnt < E_; base += 32) {
            int m = emask[b*L_ + base + lane];
            unsigned bal = __ballot_sync(FULL, pass == 0 ? (m == 1) : (m != 1));
            while (bal && cnt < E_) {
                int j = __ffs(bal) - 1; bal &= bal - 1;
                if (lane == 0) g_entpos[b*E_ + cnt] = base + j;
                cnt++;
            }
        }
    }
}

// ---------------- entity MLP layer 1 ----------------------------------------
__global__ void __launch_bounds__(128) k_entl1(const float* __restrict__ hs,
                                               const float* __restrict__ w1,
                                               const float* __restrict__ b1) {
    __shared__ float st[E_*H_];
    int b = blockIdx.y, c = blockIdx.x * 128 + threadIdx.x;
    for (int i = threadIdx.x; i < E_*H_; i += 128) {
        int e = i / H_, h = i - e*H_;
        st[i] = hs[((size_t)b*L_ + g_entpos[b*E_ + e]) * H_ + h];
    }
    __syncthreads();
    float acc[E_];
#pragma unroll
    for (int r = 0; r < E_; r++) acc[r] = 0.f;
    for (int k = 0; k < H_; k++) {
        float w = w1[(size_t)k*DFF_ + c];
#pragma unroll
        for (int r = 0; r < E_; r++) acc[r] = fmaf(st[r*H_ + k], w, acc[r]);
    }
    float bb = b1[c];
#pragma unroll
    for (int r = 0; r < E_; r++) {
        float v = acc[r] + bb;
        g_h1[((size_t)b*E_ + r)*DFF_ + c] = v > 0.f ? v : 0.01f*v;
    }
}

// ---------------- entity MLP layer 2 ----------------------------------------
__global__ void __launch_bounds__(128) k_entl2(const float* __restrict__ w2,
                                               const float* __restrict__ b2) {
    __shared__ float st[E_*DFF_];
    int b = blockIdx.y, c = blockIdx.x * 128 + threadIdx.x;
    for (int i = threadIdx.x; i < E_*DFF_; i += 128) st[i] = g_h1[(size_t)b*E_*DFF_ + i];
    __syncthreads();
    float acc[E_];
#pragma unroll
    for (int r = 0; r < E_; r++) acc[r] = 0.f;
    for (int k = 0; k < DFF_; k++) {
        float w = w2[(size_t)k*H_ + c];
#pragma unroll
        for (int r = 0; r < E_; r++) acc[r] = fmaf(st[r*DFF_ + k], w, acc[r]);
    }
    float bb = b2[c];
#pragma unroll
    for (int r = 0; r < E_; r++)
        g_entvec[((size_t)b*E_ + r)*H_ + c] = acc[r] + bb;
}

// ---------------- G[b,e,k] = sum_h span_w2[k,h]*ent_vec[b,e,h] --------------
__global__ void __launch_bounds__(128) k_gmat(const float* __restrict__ sw2) {
    __shared__ float st[E_*H_];
    int b = blockIdx.y, c = blockIdx.x * 128 + threadIdx.x;   // c: DFF index
    for (int i = threadIdx.x; i < E_*H_; i += 128) st[i] = g_entvec[(size_t)b*E_*H_ + i];
    __syncthreads();
    float acc[E_];
#pragma unroll
    for (int r = 0; r < E_; r++) acc[r] = 0.f;
    for (int h = 0; h < H_; h++) {
        float w = sw2[(size_t)c*H_ + h];
#pragma unroll
        for (int r = 0; r < E_; r++) acc[r] = fmaf(st[r*H_ + h], w, acc[r]);
    }
#pragma unroll
    for (int r = 0; r < E_; r++)
        g_G[((size_t)b*E_ + r)*DFF_ + c] = acc[r];
}

__global__ void k_cvec(const float* __restrict__ sb2) {
    int tid = threadIdx.x;
    if (tid >= B_*E_) return;
    float s = 0.f;
    for (int h = 0; h < H_; h++) s = fmaf(sb2[h], g_entvec[(size_t)tid*H_ + h], s);
    g_c[tid] = s;
}

// ---------------- pack span_w1 halves side by side: [768,1024] --------------
__global__ void k_bpack(const float* __restrict__ sw1) {
    int i = blockIdx.x * blockDim.x + threadIdx.x;
    if (i >= H_*2*DFF_) return;
    int k = i >> 10, j = i & 1023;
    g_Bpack[i] = (j < DFF_) ? sw1[(size_t)k*DFF_ + j]
                            : sw1[(size_t)(H_ + k)*DFF_ + (j - DFF_)];
}

// ---------------- GEMM: PQ[4032,1024] = word_emb[4032,768] @ Bpack ----------
__global__ void __launch_bounds__(256) k_gemm() {
    const int K = H_, Nn = 2*DFF_;
    __shared__ float sA[16][68];
    __shared__ float sB[16][64];
    int bm = blockIdx.y * 64, bn = blockIdx.x * 64;
    int tid = threadIdx.x;
    int tx = tid & 15, ty = tid >> 4;
    float acc[4][4];
#pragma unroll
    for (int i = 0; i < 4; i++)
#pragma unroll
        for (int j = 0; j < 4; j++) acc[i][j] = 0.f;

    for (int k0 = 0; k0 < K; k0 += 16) {
        {
            int r = tid >> 2, kk = (tid & 3) * 4;
            float4 v = *(const float4*)&g_word_emb[(size_t)(bm + r)*K + k0 + kk];
            sA[kk+0][r] = v.x; sA[kk+1][r] = v.y; sA[kk+2][r] = v.z; sA[kk+3][r] = v.w;
        }
        {
            int kk = tid >> 4, cc = (tid & 15) * 4;
            *(float4*)&sB[kk][cc] = *(const float4*)&g_Bpack[(size_t)(k0 + kk)*Nn + bn + cc];
        }
        __syncthreads();
#pragma unroll
        for (int k = 0; k < 16; k++) {
            float4 a  = *(float4*)&sA[k][ty*4];
            float4 bv = *(float4*)&sB[k][tx*4];
            float av[4] = {a.x, a.y, a.z, a.w};
            float bw[4] = {bv.x, bv.y, bv.z, bv.w};
#pragma unroll
            for (int i = 0; i < 4; i++)
#pragma unroll
                for (int j = 0; j < 4; j++) acc[i][j] = fmaf(av[i], bw[j], acc[i][j]);
        }
        __syncthreads();
    }
#pragma unroll
    for (int i = 0; i < 4; i++)
#pragma unroll
        for (int j = 0; j < 4; j++)
            g_PQ[(size_t)(bm + ty*4 + i)*Nn + bn + tx*4 + j] = acc[i][j];
}

// ---------------- logits + sort keys: h=leaky(P[s]+Q[e]+b1); l = h.G + c ----
__global__ void __launch_bounds__(256) k_logits(const float* __restrict__ sb1,
                                                float* __restrict__ out1) {
    __shared__ float sG[E_*DFF_];
    __shared__ float sb[DFF_];
    int b = blockIdx.y;
    for (int i = threadIdx.x; i < E_*DFF_; i += 256) sG[i] = g_G[(size_t)b*E_*DFF_ + i];
    for (int i = threadIdx.x; i < DFF_;    i += 256) sb[i] = sb1[i];
    __syncthreads();
    int warp = threadIdx.x >> 5, lane = threadIdx.x & 31;
    for (int t = 0; t < 12; t++) {
        int n = blockIdx.x*96 + warp*12 + t;
        if (n >= NSPAN) break;
        int s = g_sstart[n], e = g_send[n];
        const float* P = &g_PQ[(size_t)(b*W_ + s) * 1024];
        const float* Q = &g_PQ[(size_t)(b*W_ + e) * 1024 + 512];
        float acc[16];
#pragma unroll
        for (int i = 0; i < 16; i++) acc[i] = 0.f;
#pragma unroll
        for (int j = 0; j < 4; j++) {
            int k = lane*4 + j*128;
            float4 p  = *(const float4*)(P + k);
            float4 q  = *(const float4*)(Q + k);
            float4 bb = *(const float4*)(sb + k);
            float h0 = p.x+q.x+bb.x; h0 = h0>0.f ? h0 : 0.01f*h0;
            float h1 = p.y+q.y+bb.y; h1 = h1>0.f ? h1 : 0.01f*h1;
            float h2 = p.z+q.z+bb.z; h2 = h2>0.f ? h2 : 0.01f*h2;
            float h3 = p.w+q.w+bb.w; h3 = h3>0.f ? h3 : 0.01f*h3;
#pragma unroll
            for (int e2 = 0; e2 < 16; e2++) {
                float4 g = *(const float4*)(sG + e2*DFF_ + k);
                acc[e2] = fmaf(h0,g.x, fmaf(h1,g.y, fmaf(h2,g.z, fmaf(h3,g.w, acc[e2]))));
            }
        }
        float res = 0.f;
#pragma unroll
        for (int e2 = 0; e2 < 16; e2++) {
            float v = acc[e2];
#pragma unroll
            for (int o = 16; o; o >>= 1) v += __shfl_xor_sync(0xffffffffu, v, o);
            if (lane == e2) res = v;
        }
        if (lane < 16) {
            float lg = res + g_c[b*E_ + lane];
            int idx = n*E_ + lane;
            out1[(size_t)b*NE_ + idx] = lg;
            unsigned u = __float_as_uint(lg);
            unsigned asc = (u & 0x80000000u) ? ~u : (u | 0x80000000u);
            unsigned dsc = ~asc;
            g_keys_in[(size_t)b*NE_ + idx] =
                ((unsigned long long)b << 49) | ((unsigned long long)dsc << 17) | (unsigned)idx;
        }
    }
}

__global__ void k_zerosel(float* __restrict__ sel) {
    int i = blockIdx.x * blockDim.x + threadIdx.x;
    if (i < BNE_) sel[i] = 0.f;
}

// ---------------- greedy NMS decode: 1 warp per batch -----------------------
__global__ void k_decode(float* __restrict__ sel) {
    int b = blockIdx.x, lane = threadIdx.x;
    __shared__ unsigned long long cov[8];
    if (lane < 8) cov[lane] = 0ULL;
    __syncwarp();
    const unsigned long long* keys = g_keys_out + (size_t)b*NE_;
    for (int w0 = 0; w0 < NE_; w0 += 32) {
        unsigned long long k = keys[w0 + lane];
        unsigned dsc = (unsigned)(k >> 17);
        unsigned asc = ~dsc;
        bool pos = asc > 0x80000000u;            // logit > 0  <=>  prob > 0.5
        unsigned pb = __ballot_sync(0xffffffffu, pos);
        if (pb == 0u) break;
        int idx = (int)(k & 0x1FFFFu);
        int n = idx >> 4;
        int s = g_sstart[n], e = g_send[n];
        int wd = s >> 6, off = s & 63, len = e - s + 1;
        unsigned long long bits = (1ULL << len) - 1ULL;
        unsigned long long m0 = bits << off;
        unsigned long long m1 = (off + len > 64) ? (bits >> (64 - off)) : 0ULL;
        unsigned long long c0 = cov[wd];
        unsigned long long c1 = (wd + 1 < 8) ? cov[wd+1] : 0ULL;
        bool alive = pos && !((c0 & m0) | (c1 & m1));
        unsigned ball = __ballot_sync(0xffffffffu, alive);
        while (ball) {
            int leader = __ffs(ball) - 1;
            int lw = __shfl_sync(0xffffffffu, wd, leader);
            unsigned long long lm0 = __shfl_sync(0xffffffffu, m0, leader);
            unsigned long long lm1 = __shfl_sync(0xffffffffu, m1, leader);
            int lidx = __shfl_sync(0xffffffffu, idx, leader);
            if (lane == leader) {
                cov[lw] |= lm0;
                if (lw + 1 < 8) cov[lw+1] |= lm1;
                sel[(size_t)b*NE_ + lidx] = 1.0f;
                alive = false;
            } else if (alive && lane > leader) {
                unsigned long long o = 0ULL;
                if      (lw == wd)     o = (lm0 & m0) | (lm1 & m1);
                else if (lw == wd - 1) o = lm1 & m0;
                else if (lw == wd + 1) o = lm0 & m1;
                if (o) alive = false;
            }
            ball = __ballot_sync(0xffffffffu, alive);
        }
        __syncwarp();
        if (pb != 0xffffffffu) break;            // sorted: no positives remain
    }
}

extern "C" void kernel_launch(void* const* d_in, const int* in_sizes, int n_in,
                              void* d_out, int out_size) {
    const float* hs   = (const float*)d_in[0];
    const float* ew1  = (const float*)d_in[1];
    const float* eb1  = (const float*)d_in[2];
    const float* ew2  = (const float*)d_in[3];
    const float* eb2  = (const float*)d_in[4];
    const float* sw1  = (const float*)d_in[5];
    const float* sb1  = (const float*)d_in[6];
    const float* sw2  = (const float*)d_in[7];
    const float* sb2  = (const float*)d_in[8];
    const int* tmask  = (const int*)d_in[9];
    const int* emask  = (const int*)d_in[10];
    const int* widx   = (const int*)d_in[11];
    float* out = (float*)d_out;
    int write_sel = (out_size >= 2*BNE_);

    k_setup<<<1024, 256>>>();
    k_pool<<<B_*L_, 256>>>(hs, tmask, widx);
    k_pooldiv<<<2048, 256>>>();
    k_entscan<<<1, 256>>>(emask);
    k_entl1<<<dim3(4, B_), 128>>>(hs, ew1, eb1);
    k_entl2<<<dim3(6, B_), 128>>>(ew2, eb2);
    k_gmat<<<dim3(4, B_), 128>>>(sw2);
    k_cvec<<<1, 128>>>(sb2);
    k_bpack<<<(H_*2*DFF_ + 255)/256, 256>>>(sw1);
    k_gemm<<<dim3(16, 63), 256>>>();
    k_logits<<<dim3(63, B_), 256>>>(sb1, out);

    if (write_sel) {
        float* sel = out + BNE_;
        k_zerosel<<<(BNE_ + 255)/256, 256>>>(sel);
        void *pin, *pout, *ptmp;
        cudaGetSymbolAddress(&pin,  g_keys_in);
        cudaGetSymbolAddress(&pout, g_keys_out);
        cudaGetSymbolAddress(&ptmp, g_cub_temp);
        size_t tb = 0;
        cub::DeviceRadixSort::SortKeys(nullptr, tb,
            (const unsigned long long*)pin, (unsigned long long*)pout, BNE_, 0, 52);
        if (tb <= sizeof(g_cub_temp)) {
            cub::DeviceRadixSort::SortKeys(ptmp, tb,
                (const unsigned long long*)pin, (unsigned long long*)pout, BNE_, 0, 52);
        }
        k_decode<<<B_, 32>>>(sel);
    }
}